// round 14
// baseline (speedup 1.0000x reference)
#include <cuda_runtime.h>

// Fixed problem structure (M=512 checks, N=1024 vars, SHIFTS=(0,7,101)):
//   E = 3072 edges, check degree 6, var degree 3.
//   edges sorted by (check,var) => check c owns edges [6c, 6c+6).
#define ITERS 5
#define MCHK  512
#define NVAR  1024
#define NEDGE 3072
#define NSM   148               // sm_100a B200
#define GRID_PERSIST (4 * NSM)  // 4 blocks/SM resident -> single wave

#define LOG2E 1.4426950408889634f
#define LN2   0.6931471805599453f

// g_fast: 1 iff w_iter==1 && llr_iter==1 && w_final==1 && llr_final==1
// everywhere (verified by prepack; only 0 is ever written -> race-free).
__device__ int    g_fast = 1;
__device__ float4 g_wlt [ITERS * NEDGE];  // general path: {w0, w1, llr_iter*log2e, 0}
__device__ int2   g_sib [NEDGE];          // {sib0_b4 | sib1_b4<<16, ev} (byte offsets)
__device__ float2 g_fw  [NEDGE];          // {bitcast(fidx), w_final*ln2}

// grid = ITERS+2: blocks 0..4 pack weights, block 5 packs sib, block 6 packs fw.
__global__ void prepack_kernel(const float* __restrict__ w_iter,
                               const float* __restrict__ llr_iter,
                               const int*   __restrict__ vs_idx,
                               const int*   __restrict__ edge_var,
                               const int*   __restrict__ fin_idx,
                               const float* __restrict__ w_final,
                               const float* __restrict__ llr_final)
{
    const int c = threadIdx.x;
    const int t = blockIdx.x;
    bool ok = true;
    if (t < ITERS) {
#pragma unroll
        for (int j = 0; j < 6; ++j) {
            const int e  = 6 * c + j;
            const float w0 = w_iter[t * 2 * NEDGE + 2 * e];
            const float w1 = w_iter[t * 2 * NEDGE + 2 * e + 1];
            const float li = llr_iter[t * NVAR + edge_var[e]];
            ok = ok && (w0 == 1.0f) && (w1 == 1.0f) && (li == 1.0f);
            g_wlt[t * NEDGE + j * MCHK + c] = make_float4(w0, w1, li * LOG2E, 0.0f);
        }
    } else if (t == ITERS) {
#pragma unroll
        for (int j = 0; j < 6; ++j) {
            const int e  = 6 * c + j;
            const int s0 = vs_idx[2 * e];
            const int s1 = vs_idx[2 * e + 1];
            const int b0 = ((s0 % 6) * MCHK + s0 / 6) * 4;   // byte offsets < 2^14
            const int b1 = ((s1 % 6) * MCHK + s1 / 6) * 4;
            g_sib[j * MCHK + c] = make_int2(b0 | (b1 << 16), edge_var[e]);
        }
    } else {
#pragma unroll
        for (int k = 0; k < 2; ++k) {
            const int v = c + MCHK * k;
            ok = ok && (llr_final[v] == 1.0f);
#pragma unroll
            for (int p = 0; p < 3; ++p) {
                const int q = 3 * v + p;
                const int e = fin_idx[q];
                const float wf = w_final[q];
                ok = ok && (wf == 1.0f);
                float2 fw;
                fw.x = __int_as_float((e % 6) * MCHK + e / 6);
                fw.y = wf * LN2;
                g_fw[(k * 3 + p) * MCHK + c] = fw;
            }
        }
    }
    if (!ok) g_fast = 0;
}

// Exclusive products (pair-tree, depth 3), 0.9995 damping folded in:
// m[j] = 0.9995 * prod_{k != j} v[k]
__device__ __forceinline__ void excl_prod(const float v[6], float m[6])
{
    const float p01  = v[0] * v[1];
    const float p23  = v[2] * v[3];
    const float p45s = (0.9995f * v[4]) * v[5];
    const float B = p23 * p45s;            // excl {0,1}, scaled
    const float C = p01 * p45s;            // excl {2,3}, scaled
    const float D = 0.9995f * (p01 * p23); // excl {4,5}, scaled
    m[0] = v[1] * B;  m[1] = v[0] * B;
    m[2] = v[3] * C;  m[3] = v[2] * C;
    m[4] = v[5] * D;  m[5] = v[4] * D;
}

// General-path check update in log2 domain.
__device__ __forceinline__ void check_update_log(const float x_in[6], float c2v[6])
{
    float n[6], d[6];
#pragma unroll
    for (int j = 0; j < 6; ++j) {
        const float x  = fminf(fmaxf(x_in[j], -25.0f), 25.0f);
        const float ea = exp2f(x);
        n[j] = ea - 1.0f;
        d[j] = ea + 1.0f;
    }
    float sn[6], sd[6];
    sn[5] = 1.0f; sd[5] = 1.0f;
#pragma unroll
    for (int j = 4; j >= 0; --j) {
        sn[j] = sn[j + 1] * n[j + 1];
        sd[j] = sd[j + 1] * d[j + 1];
    }
    float pn = 0.9995f, pd = 1.0f;
#pragma unroll
    for (int j = 0; j < 6; ++j) {
        const float P = pn * sn[j];
        const float Q = pd * sd[j];
        c2v[j] = __log2f(Q + P) - __log2f(Q - P);
        pn *= n[j];
        pd *= d[j];
    }
}

// Persistent kernel: 4 blocks/SM resident, grid-stride over batch items.
// Loop body identical to the proven round-11 kernel (32 regs, no spills).
__global__ __launch_bounds__(512, 4)
void bp_decode_kernel(const float* __restrict__ llr,        // [B, N]
                      const float* __restrict__ llr_final,  // [N]
                      float*       __restrict__ out,        // [B, N]
                      int B)
{
    __shared__ float sm[2][NEDGE];      // double-buffered messages (24.6 KB)

    const int c = threadIdx.x;
    const int fastf = g_fast;

    for (int b = blockIdx.x; b < B; b += gridDim.x) {
        const float* __restrict__ llr_b = llr + (size_t)b * NVAR;

        unsigned int sibpk[6];          // packed {sb0 | sb1<<16}
        float pl[6];                    // tanh(llr/2) of this edge's variable
#pragma unroll
        for (int j = 0; j < 6; ++j) {
            const int2 s = g_sib[j * MCHK + c];      // L1-hit after first item
            sibpk[j] = (unsigned int)s.x;
            const float lvj = __ldg(&llr_b[s.y]);
            const float e = __expf(lvj);
            pl[j] = 1.0f - __fdividef(2.0f, e + 1.0f);  // NaN-safe at +-inf
        }

        int cur = 0;
        if (fastf) {
            // ===== fast path: unit weights -> tanh-domain loop, no logs =====
            float m[6];
            excl_prod(pl, m);                        // peeled iteration 0

#pragma unroll
            for (int t = 1; t < ITERS; ++t) {
                const char* smc = (const char*)sm[cur];
#pragma unroll
                for (int j = 0; j < 6; ++j) sm[cur][j * MCHK + c] = m[j];
                __syncthreads();

                float v2c[6];
#pragma unroll
                for (int j = 0; j < 6; ++j) {
                    const float ma = *(const float*)(smc + (sibpk[j] & 0xFFFFu));
                    const float mb = *(const float*)(smc + (sibpk[j] >> 16));
                    const float num1 = ma + mb;
                    const float den1 = fmaf(ma, mb, 1.0f);
                    const float num  = fmaf(pl[j], den1, num1);
                    const float den  = fmaf(pl[j], num1, den1);  // > 0
                    v2c[j] = __fdividef(num, den);
                }
                excl_prod(v2c, m);
                cur ^= 1;
            }

            // log-free epilogue (valid because w_final==1 && llr_final==1):
            //   sigmoid(sum 2*atanh(m_p) + llr) = 1/(1 + e^{-llr} prod (1-m)/(1+m))
#pragma unroll
            for (int j = 0; j < 6; ++j) sm[cur][j * MCHK + c] = m[j];
            __syncthreads();

            float* __restrict__ out_b = out + (size_t)b * NVAR;
#pragma unroll
            for (int k = 0; k < 2; ++k) {
                const int v = c + MCHK * k;
                float mp[3];
#pragma unroll
                for (int p = 0; p < 3; ++p) {
                    const float2 fw = g_fw[(k * 3 + p) * MCHK + c];
                    mp[p] = sm[cur][__float_as_int(fw.x)];
                }
                const float numr = (1.0f - mp[0]) * (1.0f - mp[1]) * (1.0f - mp[2]);
                const float denr = (1.0f + mp[0]) * (1.0f + mp[1]) * (1.0f + mp[2]);
                const float enl  = __expf(-__ldg(&llr_b[v]));
                const float tq   = enl * __fdividef(numr, denr);   // >= 0
                out_b[v] = __fdividef(1.0f, 1.0f + tq);
            }
        } else {
            // ===== general path: arbitrary weights, log2-domain messages =====
            float lv[6];
#pragma unroll
            for (int j = 0; j < 6; ++j) lv[j] = __ldg(&llr_b[g_sib[j * MCHK + c].y]);

            float c2v[6], x[6];
            {
                const float4* __restrict__ wlt = g_wlt;  // t=0, messages zero
#pragma unroll
                for (int j = 0; j < 6; ++j) x[j] = lv[j] * wlt[j * MCHK + c].z;
                check_update_log(x, c2v);
            }
#pragma unroll
            for (int t = 1; t < ITERS; ++t) {
                const float4* __restrict__ wlt = g_wlt + t * NEDGE;
                const char* smc = (const char*)sm[cur];
#pragma unroll
                for (int j = 0; j < 6; ++j) sm[cur][j * MCHK + c] = c2v[j];
                __syncthreads();
#pragma unroll
                for (int j = 0; j < 6; ++j) {
                    const float4 w  = wlt[j * MCHK + c];
                    const float  m0 = *(const float*)(smc + (sibpk[j] & 0xFFFFu));
                    const float  m1 = *(const float*)(smc + (sibpk[j] >> 16));
                    x[j] = m0 * w.x + m1 * w.y + lv[j] * w.z;
                }
                check_update_log(x, c2v);
                cur ^= 1;
            }

#pragma unroll
            for (int j = 0; j < 6; ++j) sm[cur][j * MCHK + c] = c2v[j];
            __syncthreads();

            float* __restrict__ out_b = out + (size_t)b * NVAR;
#pragma unroll
            for (int k = 0; k < 2; ++k) {
                const int v = c + MCHK * k;
                float marg = 0.0f;
#pragma unroll
                for (int p = 0; p < 3; ++p) {
                    const float2 fw = g_fw[(k * 3 + p) * MCHK + c];
                    marg += sm[cur][__float_as_int(fw.x)] * fw.y;  // *ln2 prescaled
                }
                marg += __ldg(&llr_b[v]) * llr_final[v];
                out_b[v] = __fdividef(1.0f, 1.0f + __expf(-marg));
            }
        }

        // Protect this item's epilogue smem reads from the next item's publish.
        __syncthreads();
    }
}

extern "C" void kernel_launch(void* const* d_in, const int* in_sizes, int n_in,
                              void* d_out, int out_size)
{
    // metadata order: llr, w_iter, llr_iter, w_final, llr_final,
    //                 v_sum_idx, seg_vsum, c_prod_idx, seg_cprod,
    //                 final_idx, seg_final, edge_var
    const float* llr       = (const float*)d_in[0];
    const float* w_iter    = (const float*)d_in[1];
    const float* llr_iter  = (const float*)d_in[2];
    const float* w_final   = (const float*)d_in[3];
    const float* llr_final = (const float*)d_in[4];
    const int*   vs_idx    = (const int*)  d_in[5];
    const int*   fin_idx   = (const int*)  d_in[9];
    const int*   edge_var  = (const int*)  d_in[11];
    float*       out       = (float*)d_out;

    const int B = in_sizes[0] / NVAR;
    const int grid = (B < GRID_PERSIST) ? B : GRID_PERSIST;

    prepack_kernel<<<ITERS + 2, MCHK>>>(w_iter, llr_iter, vs_idx, edge_var,
                                        fin_idx, w_final, llr_final);
    bp_decode_kernel<<<grid, MCHK>>>(llr, llr_final, out, B);
}

// round 15
// speedup vs baseline: 1.3090x; 1.3090x over previous
#include <cuda_runtime.h>

// Fixed problem structure (M=512 checks, N=1024 vars, SHIFTS=(0,7,101)):
//   E = 3072 edges, check degree 6, var degree 3.
//   edges sorted by (check,var) => check c owns edges [6c, 6c+6).
//   For each check, edges j and j+3 are the {v, v+512} pair of shift p=j%3,
//   and the pair's two siblings (per other shift) live at the SAME sibling
//   check — so float2-per-(shift,check) message slots let one LDS.64 fetch
//   siblings for both halves, one STS.64 publish both.
#define ITERS 5
#define MCHK  512
#define NVAR  1024
#define NEDGE 3072
#define NSLOT (3 * MCHK)        // float2 slots (pair messages)

#define LOG2E 1.4426950408889634f
#define LN2   0.6931471805599453f

// g_fast: 1 iff w_iter==1 && llr_iter==1 && w_final==1 && llr_final==1
// everywhere (verified by prepack; only 0 is ever written -> race-free).
__device__ int    g_fast = 1;
__device__ float4 g_wlt [ITERS * NEDGE];  // general path: {w0, w1, llr_iter*log2e, 0}
__device__ int2   g_sib [NSLOT];          // {off0_b8 | off1_b8<<16, v_base} per (shift,check)
__device__ float2 g_fw  [NEDGE];          // {bitcast(byte off into float2 layout), w_final*ln2}

// grid = ITERS+2: blocks 0..4 pack weights, block 5 packs sib pairs, block 6 fw.
__global__ void prepack_kernel(const float* __restrict__ w_iter,
                               const float* __restrict__ llr_iter,
                               const int*   __restrict__ vs_idx,
                               const int*   __restrict__ edge_var,
                               const int*   __restrict__ fin_idx,
                               const float* __restrict__ w_final,
                               const float* __restrict__ llr_final)
{
    const int c = threadIdx.x;
    const int t = blockIdx.x;
    bool ok = true;
    if (t < ITERS) {
#pragma unroll
        for (int j = 0; j < 6; ++j) {
            const int e  = 6 * c + j;
            const float w0 = w_iter[t * 2 * NEDGE + 2 * e];
            const float w1 = w_iter[t * 2 * NEDGE + 2 * e + 1];
            const float li = llr_iter[t * NVAR + edge_var[e]];
            ok = ok && (w0 == 1.0f) && (w1 == 1.0f) && (li == 1.0f);
            g_wlt[t * NEDGE + j * MCHK + c] = make_float4(w0, w1, li * LOG2E, 0.0f);
        }
    } else if (t == ITERS) {
        // pair p of check c <-> half-0 edge e = 6c + p; siblings of the pair
        // live at (shift p', check c') float2 slots -> byte offsets (x8).
#pragma unroll
        for (int p = 0; p < 3; ++p) {
            const int e  = 6 * c + p;            // half-0 edge (var < 512)
            const int s0 = vs_idx[2 * e];
            const int s1 = vs_idx[2 * e + 1];
            const int o0 = (((s0 % 6) % 3) * MCHK + s0 / 6) * 8;  // < 12288
            const int o1 = (((s1 % 6) % 3) * MCHK + s1 / 6) * 8;
            g_sib[p * MCHK + c] = make_int2(o0 | (o1 << 16), edge_var[e]);
        }
    } else {
#pragma unroll
        for (int k = 0; k < 2; ++k) {
            const int v = c + MCHK * k;
            ok = ok && (llr_final[v] == 1.0f);
#pragma unroll
            for (int p = 0; p < 3; ++p) {
                const int q = 3 * v + p;
                const int e = fin_idx[q];
                const float wf = w_final[q];
                ok = ok && (wf == 1.0f);
                const int j = e % 6;
                // byte addr of this edge's message: slot (j%3, e/6), comp j/3
                float2 fw;
                fw.x = __int_as_float(((j % 3) * MCHK + e / 6) * 8 + (j / 3) * 4);
                fw.y = wf * LN2;
                g_fw[(k * 3 + p) * MCHK + c] = fw;
            }
        }
    }
    if (!ok) g_fast = 0;
}

// Exclusive products (pair-tree, depth 3), 0.9995 damping folded in:
// m[j] = 0.9995 * prod_{k != j} v[k]
__device__ __forceinline__ void excl_prod(const float v[6], float m[6])
{
    const float p01  = v[0] * v[1];
    const float p23  = v[2] * v[3];
    const float p45s = (0.9995f * v[4]) * v[5];
    const float B = p23 * p45s;            // excl {0,1}, scaled
    const float C = p01 * p45s;            // excl {2,3}, scaled
    const float D = 0.9995f * (p01 * p23); // excl {4,5}, scaled
    m[0] = v[1] * B;  m[1] = v[0] * B;
    m[2] = v[3] * C;  m[3] = v[2] * C;
    m[4] = v[5] * D;  m[5] = v[4] * D;
}

// General-path check update in log2 domain.
__device__ __forceinline__ void check_update_log(const float x_in[6], float c2v[6])
{
    float n[6], d[6];
#pragma unroll
    for (int j = 0; j < 6; ++j) {
        const float x  = fminf(fmaxf(x_in[j], -25.0f), 25.0f);
        const float ea = exp2f(x);
        n[j] = ea - 1.0f;
        d[j] = ea + 1.0f;
    }
    float sn[6], sd[6];
    sn[5] = 1.0f; sd[5] = 1.0f;
#pragma unroll
    for (int j = 4; j >= 0; --j) {
        sn[j] = sn[j + 1] * n[j + 1];
        sd[j] = sd[j + 1] * d[j + 1];
    }
    float pn = 0.9995f, pd = 1.0f;
#pragma unroll
    for (int j = 0; j < 6; ++j) {
        const float P = pn * sn[j];
        const float Q = pd * sd[j];
        c2v[j] = __log2f(Q + P) - __log2f(Q - P);
        pn *= n[j];
        pd *= d[j];
    }
}

__device__ __forceinline__ float tanh_half(float x)  // tanh(x/2), NaN-safe
{
    const float e = __expf(x);
    return 1.0f - __fdividef(2.0f, e + 1.0f);
}

// One batch item per block (the proven R11 dispatch: grid=B, 4 blocks/SM).
// Messages stored as float2 {half0, half1} per (shift, check) slot:
// 3 STS.64 + 6 LDS.64 per iteration instead of 6 STS + 12 LDS.
__global__ __launch_bounds__(512, 4)
void bp_decode_kernel(const float* __restrict__ llr,        // [B, N]
                      const float* __restrict__ llr_final,  // [N]
                      float*       __restrict__ out)        // [B, N]
{
    __shared__ float2 sm[2][NSLOT];     // double-buffered pair messages (24.6 KB)

    const int b = blockIdx.x;
    const int c = threadIdx.x;
    const float* __restrict__ llr_b = llr + (size_t)b * NVAR;

    unsigned int sibpk[3];              // packed {off0_b8 | off1_b8<<16}
    float pl[6];                        // [2p+h] = tanh(llr/2), h=0: v, h=1: v+512
#pragma unroll
    for (int p = 0; p < 3; ++p) {
        const int2 s = g_sib[p * MCHK + c];          // 1 LDG.64 per pair
        sibpk[p] = (unsigned int)s.x;
        pl[2 * p]     = tanh_half(__ldg(&llr_b[s.y]));
        pl[2 * p + 1] = tanh_half(__ldg(&llr_b[s.y + MCHK]));
    }

    int cur = 0;
    if (g_fast) {
        // ======= fast path: unit weights -> tanh-domain loop, no logs =======
        float m[6];
        excl_prod(pl, m);                            // peeled iteration 0

#pragma unroll
        for (int t = 1; t < ITERS; ++t) {
            char* smc = (char*)sm[cur];
#pragma unroll
            for (int p = 0; p < 3; ++p)
                *(float2*)(smc + (p * MCHK + c) * 8) =
                    make_float2(m[2 * p], m[2 * p + 1]);        // STS.64
            __syncthreads();

            float v2c[6];
#pragma unroll
            for (int p = 0; p < 3; ++p) {
                const float2 A  = *(const float2*)(smc + (sibpk[p] & 0xFFFFu));
                const float2 Bv = *(const float2*)(smc + (sibpk[p] >> 16));
                {   // half 0 (var v)
                    const float s1_ = A.x + Bv.x;
                    const float d1_ = fmaf(A.x, Bv.x, 1.0f);
                    const float nu  = fmaf(pl[2 * p], d1_, s1_);
                    const float de  = fmaf(pl[2 * p], s1_, d1_);   // > 0
                    v2c[2 * p] = __fdividef(nu, de);
                }
                {   // half 1 (var v+512)
                    const float s1_ = A.y + Bv.y;
                    const float d1_ = fmaf(A.y, Bv.y, 1.0f);
                    const float nu  = fmaf(pl[2 * p + 1], d1_, s1_);
                    const float de  = fmaf(pl[2 * p + 1], s1_, d1_);
                    v2c[2 * p + 1] = __fdividef(nu, de);
                }
            }
            excl_prod(v2c, m);
            cur ^= 1;
        }

        // log-free epilogue (valid because w_final==1 && llr_final==1):
        //   sigmoid(sum 2*atanh(m_p) + llr) = 1/(1 + e^{-llr} prod (1-m)/(1+m))
        char* smc = (char*)sm[cur];
#pragma unroll
        for (int p = 0; p < 3; ++p)
            *(float2*)(smc + (p * MCHK + c) * 8) =
                make_float2(m[2 * p], m[2 * p + 1]);
        __syncthreads();

        float* __restrict__ out_b = out + (size_t)b * NVAR;
#pragma unroll
        for (int k = 0; k < 2; ++k) {
            const int v = c + MCHK * k;
            float mp[3];
#pragma unroll
            for (int p = 0; p < 3; ++p) {
                const float2 fw = g_fw[(k * 3 + p) * MCHK + c];
                mp[p] = *(const float*)(smc + __float_as_int(fw.x));
            }
            const float numr = (1.0f - mp[0]) * (1.0f - mp[1]) * (1.0f - mp[2]);
            const float denr = (1.0f + mp[0]) * (1.0f + mp[1]) * (1.0f + mp[2]);
            const float enl  = __expf(-__ldg(&llr_b[v]));
            const float tq   = enl * __fdividef(numr, denr);    // >= 0
            out_b[v] = __fdividef(1.0f, 1.0f + tq);
        }
    } else {
        // ======= general path: arbitrary weights, log2-domain messages =======
        float lv[6];
#pragma unroll
        for (int p = 0; p < 3; ++p) {
            const int vb = g_sib[p * MCHK + c].y;
            lv[2 * p]     = __ldg(&llr_b[vb]);
            lv[2 * p + 1] = __ldg(&llr_b[vb + MCHK]);
        }

        float c2v[6], x[6];
        {
            const float4* __restrict__ wlt = g_wlt;  // t=0, messages zero
#pragma unroll
            for (int p = 0; p < 3; ++p) {
                x[2 * p]     = lv[2 * p]     * wlt[p * MCHK + c].z;       // j=p
                x[2 * p + 1] = lv[2 * p + 1] * wlt[(p + 3) * MCHK + c].z; // j=p+3
            }
            check_update_log(x, c2v);
        }
#pragma unroll
        for (int t = 1; t < ITERS; ++t) {
            const float4* __restrict__ wlt = g_wlt + t * NEDGE;
            char* smc = (char*)sm[cur];
#pragma unroll
            for (int p = 0; p < 3; ++p)
                *(float2*)(smc + (p * MCHK + c) * 8) =
                    make_float2(c2v[2 * p], c2v[2 * p + 1]);
            __syncthreads();
#pragma unroll
            for (int p = 0; p < 3; ++p) {
                const float2 A  = *(const float2*)(smc + (sibpk[p] & 0xFFFFu));
                const float2 Bv = *(const float2*)(smc + (sibpk[p] >> 16));
                const float4 w0 = wlt[p * MCHK + c];         // edge j=p   (half 0)
                const float4 w1 = wlt[(p + 3) * MCHK + c];   // edge j=p+3 (half 1)
                x[2 * p]     = A.x * w0.x + Bv.x * w0.y + lv[2 * p]     * w0.z;
                x[2 * p + 1] = A.y * w1.x + Bv.y * w1.y + lv[2 * p + 1] * w1.z;
            }
            check_update_log(x, c2v);
            cur ^= 1;
        }

        char* smc = (char*)sm[cur];
#pragma unroll
        for (int p = 0; p < 3; ++p)
            *(float2*)(smc + (p * MCHK + c) * 8) =
                make_float2(c2v[2 * p], c2v[2 * p + 1]);
        __syncthreads();

        float* __restrict__ out_b = out + (size_t)b * NVAR;
#pragma unroll
        for (int k = 0; k < 2; ++k) {
            const int v = c + MCHK * k;
            float marg = 0.0f;
#pragma unroll
            for (int p = 0; p < 3; ++p) {
                const float2 fw = g_fw[(k * 3 + p) * MCHK + c];
                marg += *(const float*)(smc + __float_as_int(fw.x)) * fw.y;
            }
            marg += __ldg(&llr_b[v]) * llr_final[v];
            out_b[v] = __fdividef(1.0f, 1.0f + __expf(-marg));
        }
    }
}

extern "C" void kernel_launch(void* const* d_in, const int* in_sizes, int n_in,
                              void* d_out, int out_size)
{
    // metadata order: llr, w_iter, llr_iter, w_final, llr_final,
    //                 v_sum_idx, seg_vsum, c_prod_idx, seg_cprod,
    //                 final_idx, seg_final, edge_var
    const float* llr       = (const float*)d_in[0];
    const float* w_iter    = (const float*)d_in[1];
    const float* llr_iter  = (const float*)d_in[2];
    const float* w_final   = (const float*)d_in[3];
    const float* llr_final = (const float*)d_in[4];
    const int*   vs_idx    = (const int*)  d_in[5];
    const int*   fin_idx   = (const int*)  d_in[9];
    const int*   edge_var  = (const int*)  d_in[11];
    float*       out       = (float*)d_out;

    const int B = in_sizes[0] / NVAR;

    prepack_kernel<<<ITERS + 2, MCHK>>>(w_iter, llr_iter, vs_idx, edge_var,
                                        fin_idx, w_final, llr_final);
    bp_decode_kernel<<<B, MCHK>>>(llr, llr_final, out);
}